// round 16
// baseline (speedup 1.0000x reference)
#include <cuda_runtime.h>
#include <cstdint>

#define BS 4
#define SQ 1024
#define CH 64
#define UN 32
#define TSPAN 68                     // 4 query rows + 64 window
#define NBLK 256                     // s-blocks per batch
#define GRID (BS * NBLK)
#define THREADS 256

__device__ float g_k[BS * SQ * UN];
__device__ unsigned g_flag[GRID];    // monotonic; +1 per block per launch

__device__ __forceinline__ float htanh(float x) {
    float y;
    asm("tanh.approx.f32 %0, %1;" : "=f"(y) : "f"(x));
    return y;
}

// shared pool (floats)
#define OFF_XTS  0                         // xts [68][64] swizzled = 4352
#define OFF_U1   4352                      // ph1: wts[32][68]+wxs[32][68]=4352
                                           // ph2: ks[68][32]=2176 + vs[16][68]=1088
#define OFF_QS   (4352 + 4352)             // qs [4][32] = 128
#define OFF_AS   (OFF_QS + 128)            // a_s [4][64] = 256
#define OFF_WAS  (OFF_AS + 256)            // 32
#define OFF_SUM  (OFF_WAS + 32)            // 8
#define SMEM_FLOATS (OFF_SUM + 8)          // 9128 floats = 36.5KB -> 6 blocks/SM

__global__ __launch_bounds__(THREADS, 6) void fused_kernel(
    const float* __restrict__ x,
    const float* __restrict__ Wt,
    const float* __restrict__ Wx,
    const float* __restrict__ bh,
    const float* __restrict__ wa,
    float* __restrict__ vout,
    float* __restrict__ aout)
{
    __shared__ __align__(16) float pool[SMEM_FLOATS];

    float* xts  = pool + OFF_XTS;   // [ti][c], stride 64, 16B XOR swizzle
    float* qs   = pool + OFF_QS;    // [r][u]
    float* was  = pool + OFF_WAS;
    float* sumb = pool + OFF_SUM;   // [r*2+h]

    int b = blockIdx.x >> 8;
    int sblk = blockIdx.x & 255;
    int s0 = sblk << 2;
    int tid = threadIdx.x;
    int wid = tid >> 5, ln = tid & 31;
    int tlo = s0 - 32;

    // ---- top: input LDG wave only ----
    {
        float* wts = pool + OFF_U1;          // [u][c], stride 68 (odd 16B units)
        float* wxs = wts + UN * 68;
        const float4* wt4 = (const float4*)Wt;
        const float4* wx4 = (const float4*)Wx;
#pragma unroll
        for (int i = 0; i < 2; i++) {
            int l = tid + i * 256;
            int u = l >> 4, g = l & 15;
            *(float4*)&wts[u * 68 + g * 4] = wt4[l];
            *(float4*)&wxs[u * 68 + g * 4] = wx4[l];
        }
        if (tid < UN) was[tid] = wa[tid];

        int gq = tid & 7;
        const float* xbase = x + (size_t)b * CH * SQ;
#pragma unroll
        for (int half = 0; half < 2; half++) {
            int cc = (tid >> 3) + half * 32;
            int gb = cc >> 2, clo = cc & 3;
            const float* xb = xbase + cc * SQ;
            if (sblk >= 8 && sblk <= 246) {
                const float4* xb4 = (const float4*)(xb + tlo);   // tlo%4==0
#pragma unroll
                for (int f = 0; f < 3; f++) {
                    int fi = gq + f * 8;
                    if (fi < 17) {                               // 68/4 rows
                        float4 v = xb4[fi];
                        int t0 = fi << 2;
                        xts[(t0 + 0) * 64 + (((((t0 + 0) & 7) ^ gb) << 2) | clo)] = v.x;
                        xts[(t0 + 1) * 64 + (((((t0 + 1) & 7) ^ gb) << 2) | clo)] = v.y;
                        xts[(t0 + 2) * 64 + (((((t0 + 2) & 7) ^ gb) << 2) | clo)] = v.z;
                        xts[(t0 + 3) * 64 + (((((t0 + 3) & 7) ^ gb) << 2) | clo)] = v.w;
                    }
                }
            } else {
#pragma unroll
                for (int p = 0; p < 9; p++) {
                    int ti = p * 8 + gq;
                    if (ti < TSPAN) {
                        int tc = min(max(tlo + ti, 0), SQ - 1);
                        xts[ti * 64 + (((gb ^ gq) << 2) | clo)] = xb[tc];  // ti&7==gq
                    }
                }
            }
        }
    }
    __syncthreads();                         // SYNC_A

    // ---- phase 1: warps 0-3 q rows 0-3; warps 4-7 k rows 0-3 ----
    {
        const float* wts = pool + OFF_U1;
        const float* wxs = wts + UN * 68;
        int ss = wid & 3;                    // own row
        const float* wrow = (wid < 4) ? &wts[ln * 68] : &wxs[ln * 68];
        const float4* xp = (const float4*)&xts[(32 + ss) * 64];   // (32+ss)&7 == ss
        const float4* wp = (const float4*)wrow;
        float a0 = 0.f, a1 = 0.f, a2 = 0.f, a3 = 0.f;
#pragma unroll
        for (int gg = 0; gg < 16; gg++) {    // stored (swizzled) group
            float4 x4 = xp[gg];              // broadcast
            int wg = (gg & 8) | ((gg & 7) ^ ss);
            float4 w4 = wp[wg];
            a0 = fmaf(x4.x, w4.x, a0); a1 = fmaf(x4.y, w4.y, a1);
            a2 = fmaf(x4.z, w4.z, a2); a3 = fmaf(x4.w, w4.w, a3);
        }
        float res = (a0 + a1) + (a2 + a3);
        if (wid < 4) {
            qs[ss * 32 + ln] = res;
        } else {
            g_k[((size_t)b * SQ + s0 + ss) * UN + ln] = res + bh[ln];  // bh folded
        }
    }
    __syncthreads();                         // SYNC_B: all k rows stored

    // ---- warp 0: release + 17-owner parallel spin + full ks fill.
    //      warps 1-7: zero the 4 a-rows. ----
    float* ks = pool + OFF_U1;               // [ti][u], stride 32, XOR swizzle
    float* vs = ks + TSPAN * 32;             // [pseg][c], stride 68
    if (wid == 0) {
        unsigned v = 0;
        if (ln == 0) {
            __threadfence();                 // release own k stores
            v = atomicAdd(&g_flag[blockIdx.x], 1u);   // old value = launchN-1
        }
        v = __shfl_sync(0xffffffffu, v, 0);
        if (ln < 17) {                       // 17 owners: sblk-8 .. sblk+8
            int owner = min(max(sblk - 8 + ln, 0), NBLK - 1);
            volatile unsigned* f = (volatile unsigned*)&g_flag[(b << 8) + owner];
            while (*f <= v) { }
            __threadfence();                 // acquire
        }
        __syncwarp();
        const float4* gk4 = (const float4*)g_k;
#pragma unroll
        for (int rep = 0; rep < 17; rep++) { // 544 float4 over 32 lanes
            int lin = ln + rep * 32;
            int ti = lin >> 3, gq = lin & 7;
            int tc = min(max(tlo + ti, 0), SQ - 1);
            *(float4*)&ks[ti * 32 + ((gq ^ (ti & 7)) << 2)] =
                gk4[((size_t)b * SQ + tc) * 8 + gq];
        }
    } else {
        float4 zz = make_float4(0.f, 0.f, 0.f, 0.f);
        float4* abase = (float4*)(aout + (((size_t)b * SQ + s0) << 10));
        for (int idx = tid - 32; idx < 1024; idx += 224)
            abase[idx] = zz;                 // 4 rows x 256 float4
    }
    __syncthreads();                         // SYNC_D: ks ready, zeros ordered

    // ---- scores: warp (r = wid>>1, h = wid&1); one score per lane ----
    int r = wid >> 1;
    int h = wid & 1;
    int s = s0 + r;
    int j = (h << 5) + ln;
    int t = s - 32 + j;
    bool valid = (t >= 0) && (t < SQ);
    int ti = r + j;                          // <= 66

    const float* kb = &ks[ti * 32];
    int sw = ti & 7;
    const float4* qp = (const float4*)&qs[r * 32];
    const float4* wap = (const float4*)was;
    float acc0 = 0.f, acc1 = 0.f;
#pragma unroll
    for (int g = 0; g < 8; g++) {
        float4 q4 = qp[g];
        float4 w4 = wap[g];
        float4 k4 = *(const float4*)&kb[((g ^ sw) << 2)];
        acc0 = fmaf(w4.x, htanh(q4.x + k4.x), acc0);
        acc1 = fmaf(w4.y, htanh(q4.y + k4.y), acc1);
        acc0 = fmaf(w4.z, htanh(q4.z + k4.z), acc0);
        acc1 = fmaf(w4.w, htanh(q4.w + k4.w), acc1);
    }

    // softmax (no max-shift: scores bounded by sum|wa|; shift cancels
    // except through eps -> rel err <= ~1.3e-5)
    float* a_s = pool + OFF_AS;
    float e = valid ? __expf(acc0 + acc1) : 0.f;
    float sm = e;
#pragma unroll
    for (int o = 16; o > 0; o >>= 1) sm += __shfl_xor_sync(0xffffffffu, sm, o);
    if (ln == 0) sumb[(r << 1) + h] = sm;
    a_s[(r << 6) + j] = e;                   // unnormalized
    __syncthreads();                         // SYNC_E

    float inv = __fdividef(1.f, sumb[r << 1] + sumb[(r << 1) + 1] + 1e-7f);

    // a window write (zeros stored before SYNC_D -> ordered)
    if (valid)
        aout[(((size_t)b * SQ + s) << 10) + t] = e * inv;

    // ---- v pass: warp (r,h): 32 lanes = 16 c-groups x 2 j-quarters ----
    {
        int cgrp = ln & 15;                  // 4 channels
        int jq = ln >> 4;                    // 16 j each
        int j0 = (h << 5) + (jq << 4);
        float4 vacc = make_float4(0.f, 0.f, 0.f, 0.f);
#pragma unroll
        for (int it = 0; it < 16; it++) {
            int jj = j0 + it;
            int row = r + jj;
            float av = a_s[(r << 6) + jj];
            float4 x4 = *(const float4*)&xts[row * 64 + ((cgrp ^ (row & 7)) << 2)];
            vacc.x = fmaf(av, x4.x, vacc.x);
            vacc.y = fmaf(av, x4.y, vacc.y);
            vacc.z = fmaf(av, x4.z, vacc.z);
            vacc.w = fmaf(av, x4.w, vacc.w);
        }
        vacc.x *= inv; vacc.y *= inv; vacc.z *= inv; vacc.w *= inv;
        int pseg = (wid << 1) | jq;          // ((r*2+h)*2+jq) = 4 partials/row
        *(float4*)&vs[pseg * 68 + (cgrp << 2)] = vacc;
    }
    __syncthreads();                         // SYNC_F

    // ---- combine 4 partials per (row, c) + coalesced v write ----
    {
        int c = tid >> 2, i = tid & 3;       // 64 c x 4 rows
        int base = (i << 2) * 68 + c;
        float vsum = (vs[base] + vs[base + 68]) +
                     (vs[base + 136] + vs[base + 204]);
        vout[(size_t)b * CH * SQ + c * SQ + s0 + i] = vsum;
    }
}

extern "C" void kernel_launch(void* const* d_in, const int* in_sizes, int n_in,
                              void* d_out, int out_size) {
    (void)in_sizes; (void)n_in; (void)out_size;
    const float* x  = (const float*)d_in[0];
    const float* Wt = (const float*)d_in[1];
    const float* Wx = (const float*)d_in[2];
    const float* Wa = (const float*)d_in[3];
    // d_in[4] = Wa_b: cancels exactly in the softmax, unused
    const float* bh = (const float*)d_in[5];

    float* vout = (float*)d_out;                     // (B, C, S)
    float* aout = vout + (size_t)BS * CH * SQ;       // (B, S, S)

    fused_kernel<<<GRID, THREADS>>>(x, Wt, Wx, bh, Wa, vout, aout);
}